// round 13
// baseline (speedup 1.0000x reference)
#include <cuda_runtime.h>
#include <cuda_bf16.h>
#include <cstdint>

#define NTOK 32768
#define LVLS 4
#define NF   512
#define NH   512
#define ND   64
#define NCB  4096

// ---------------- scratch (device globals; no allocation allowed) ----------
__device__ __align__(16) __nv_bfloat16 g_xb [NTOK * 2048];            // x bf16
__device__ __align__(16) __nv_bfloat16 g_hb [LVLS * NTOK * NH];       // 128MB
__device__ __align__(16) __nv_bfloat16 g_zb [LVLS * NTOK * ND];
__device__ __align__(16) __nv_bfloat16 g_w1t[LVLS * NH * NF];         // [N][K]
__device__ __align__(16) __nv_bfloat16 g_w2t[LVLS * ND * NH];
__device__ __align__(16) __nv_bfloat16 g_d1t[LVLS * NH * ND];
__device__ __align__(16) __nv_bfloat16 g_d2t[LVLS * NF * NH];
__device__ __align__(16) __nv_bfloat16 g_cbb[LVLS * NCB * ND];
__device__ float  g_cnorm[LVLS * NCB];
__device__ double g_mse_acc;
__device__ double g_commit_acc;

// ---------------- helpers ---------------------------------------------------
__device__ __forceinline__ uint32_t smem_to_u32(const void* p) {
    uint32_t a;
    asm("{ .reg .u64 t; cvta.to.shared.u64 t, %1; cvt.u32.u64 %0, t; }" : "=r"(a) : "l"(p));
    return a;
}
__device__ __forceinline__ uint32_t sw128(uint32_t o) { return o ^ ((o >> 3) & 0x70); }

__device__ __forceinline__ void cp16(uint32_t dst, const void* src) {
    asm volatile("cp.async.cg.shared.global [%0], [%1], 16;" :: "r"(dst), "l"(src) : "memory");
}
#define CP_COMMIT() asm volatile("cp.async.commit_group;" ::: "memory")
#define CP_WAIT0()  asm volatile("cp.async.wait_group 0;" ::: "memory")
#define CP_WAIT1()  asm volatile("cp.async.wait_group 1;" ::: "memory")

__device__ __forceinline__ void ldsm_x4(uint32_t* r, uint32_t addr) {
    asm volatile("ldmatrix.sync.aligned.m8n8.x4.shared.b16 {%0,%1,%2,%3}, [%4];"
        : "=r"(r[0]), "=r"(r[1]), "=r"(r[2]), "=r"(r[3]) : "r"(addr));
}
__device__ __forceinline__ void mma16816(float* c, const uint32_t* a, const uint32_t* b) {
    asm volatile("mma.sync.aligned.m16n8k16.row.col.f32.bf16.bf16.f32 "
        "{%0,%1,%2,%3}, {%4,%5,%6,%7}, {%8,%9}, {%0,%1,%2,%3};"
        : "+f"(c[0]), "+f"(c[1]), "+f"(c[2]), "+f"(c[3])
        : "r"(a[0]), "r"(a[1]), "r"(a[2]), "r"(a[3]), "r"(b[0]), "r"(b[1]));
}

// ---------------- small kernels ---------------------------------------------
__global__ void conv_bf16_kernel(const float4* __restrict__ in, uint2* __restrict__ out, int n4) {
    int i = blockIdx.x * blockDim.x + threadIdx.x;
    if (i < n4) {
        float4 v = in[i];
        __nv_bfloat162 a = __floats2bfloat162_rn(v.x, v.y);
        __nv_bfloat162 b = __floats2bfloat162_rn(v.z, v.w);
        uint2 o; o.x = *(uint32_t*)&a; o.y = *(uint32_t*)&b;
        out[i] = o;
    }
}

// codebook: fp32 -> bf16 copy + squared norms + accumulator init, one pass
__global__ void cb_prep_kernel(const float* __restrict__ CB, __nv_bfloat16* __restrict__ CBb) {
    int c = blockIdx.x * blockDim.x + threadIdx.x;   // over LVLS*NCB rows
    if (c == 0) { g_mse_acc = 0.0; g_commit_acc = 0.0; }
    if (c < LVLS * NCB) {
        const float4* p = (const float4*)(CB + (size_t)c * ND);
        __nv_bfloat162* o = (__nv_bfloat162*)(CBb + (size_t)c * ND);
        float s = 0.f;
#pragma unroll
        for (int k = 0; k < ND / 4; k++) {
            float4 v = p[k];
            s += v.x * v.x + v.y * v.y + v.z * v.z + v.w * v.w;
            o[k * 2]     = __floats2bfloat162_rn(v.x, v.y);
            o[k * 2 + 1] = __floats2bfloat162_rn(v.z, v.w);
        }
        g_cnorm[c] = s;
    }
}

// two 512x512 weight sets (ew1, dw2) in one launch: blockIdx.z in [0, 2*LVLS)
__global__ void transpose_conv2_kernel(const float* __restrict__ Wa, __nv_bfloat16* __restrict__ Oa,
                                       const float* __restrict__ Wb, __nv_bfloat16* __restrict__ Ob) {
    __shared__ float ts[32][33];
    int z = blockIdx.z;
    const float* W  = (z < LVLS) ? Wa + (size_t)z * 512 * 512 : Wb + (size_t)(z - LVLS) * 512 * 512;
    __nv_bfloat16* O = (z < LVLS) ? Oa + (size_t)z * 512 * 512 : Ob + (size_t)(z - LVLS) * 512 * 512;
    int n0 = blockIdx.x * 32, k0 = blockIdx.y * 32;
    int tx = threadIdx.x, ty = threadIdx.y;
#pragma unroll
    for (int i = 0; i < 32; i += 8) ts[ty + i][tx] = W[(size_t)(k0 + ty + i) * 512 + n0 + tx];
    __syncthreads();
#pragma unroll
    for (int i = 0; i < 32; i += 8) O[(size_t)(n0 + ty + i) * 512 + k0 + tx] = __float2bfloat16(ts[tx][ty + i]);
}

// two thin weight sets (ew2: K=512,N=64 ; dw1: K=64,N=512), one launch.
// grid (16, 16, 2*LVLS) with per-shape guards (excess blocks exit).
__global__ void transpose_thin_kernel(const float* __restrict__ Wa, __nv_bfloat16* __restrict__ Oa,
                                      const float* __restrict__ Wb, __nv_bfloat16* __restrict__ Ob) {
    __shared__ float ts[32][33];
    int z = blockIdx.z;
    int K, N; const float* W; __nv_bfloat16* O;
    if (z < LVLS) { K = 512; N = 64;  W = Wa + (size_t)z * 512 * 64;  O = Oa + (size_t)z * 512 * 64; }
    else          { K = 64;  N = 512; W = Wb + (size_t)(z - LVLS) * 64 * 512; O = Ob + (size_t)(z - LVLS) * 64 * 512; }
    int n0 = blockIdx.x * 32, k0 = blockIdx.y * 32;
    if (n0 >= N || k0 >= K) return;
    int tx = threadIdx.x, ty = threadIdx.y;
#pragma unroll
    for (int i = 0; i < 32; i += 8) ts[ty + i][tx] = W[(size_t)(k0 + ty + i) * N + n0 + tx];
    __syncthreads();
#pragma unroll
    for (int i = 0; i < 32; i += 8) O[(size_t)(n0 + ty + i) * K + k0 + tx] = __float2bfloat16(ts[tx][ty + i]);
}

// ---------------- mma.sync GEMM, level-batched (blockIdx.z), 3-stage --------
// C[128-row tile, BN] = A @ Bt^T (+bias, relu). A bf16 row-major (lda),
// Bt bf16 [N][K] K-major. BK=64, K compile-time.
template<int K, int BN, int WM, int WN, bool RELU>
__global__ void __launch_bounds__(256, 2) gemm_mma(
    const __nv_bfloat16* __restrict__ A0, int lda, size_t aLvl,
    const __nv_bfloat16* __restrict__ Bt0, size_t bLvl,
    const float* __restrict__ bias0, int biasLvl,
    __nv_bfloat16* __restrict__ C0, int ldc, size_t cLvl)
{
    constexpr int WTM = 128 / WM;
    constexpr int WTN = BN / WN;
    constexpr int MI  = WTM / 16;
    constexpr int NJ  = WTN / 8;
    constexpr int ABYTES = 128 * 128;
    constexpr int BBYTES = BN * 128;
    constexpr int STAGE  = ABYTES + BBYTES;
    constexpr int T = K / 64;

    extern __shared__ char sm[];
    const uint32_t smb = smem_to_u32(sm);

    const int lvl = blockIdx.z;
    const __nv_bfloat16* A    = A0 + (size_t)lvl * aLvl;
    const __nv_bfloat16* Bt   = Bt0 + (size_t)lvl * bLvl;
    const float*         bias = bias0 + (size_t)lvl * biasLvl;
    __nv_bfloat16*       C    = C0 + (size_t)lvl * cLvl;

    const int tid  = threadIdx.x;
    const int lane = tid & 31;
    const int wid  = tid >> 5;
    const int wm   = wid / WN;
    const int wn   = wid % WN;
    const int rowBase = blockIdx.y * 128;
    const int colBase = blockIdx.x * BN;

    const char* Abase = (const char*)(A + (size_t)rowBase * lda);
    const char* Bbase = (const char*)(Bt + (size_t)colBase * K);

    auto copy_stage = [&](int t) {
        const uint32_t sb = smb + (t % 3) * STAGE;
        const char* Ag = Abase + t * 128;
        for (int idx = tid; idx < 128 * 8; idx += 256) {
            int r = idx >> 3, u = idx & 7;
            cp16(sb + sw128(r * 128 + u * 16), Ag + (size_t)r * lda * 2 + u * 16);
        }
        const char* Bg = Bbase + t * 128;
        for (int idx = tid; idx < BN * 8; idx += 256) {
            int r = idx >> 3, u = idx & 7;
            cp16(sb + ABYTES + sw128(r * 128 + u * 16), Bg + (size_t)r * K * 2 + u * 16);
        }
        CP_COMMIT();
    };

    float acc[MI][NJ][4];
#pragma unroll
    for (int i = 0; i < MI; i++)
#pragma unroll
        for (int j = 0; j < NJ; j++)
#pragma unroll
            for (int k = 0; k < 4; k++) acc[i][j][k] = 0.f;

    copy_stage(0);
    if (T > 1) copy_stage(1);

#pragma unroll
    for (int t = 0; t < T; t++) {
        if (t + 1 < T) CP_WAIT1(); else CP_WAIT0();
        __syncthreads();
        if (t + 2 < T) copy_stage(t + 2);
        const uint32_t baseA = smb + (t % 3) * STAGE;
        const uint32_t baseB = baseA + ABYTES;
#pragma unroll
        for (int ks = 0; ks < 4; ks++) {
            uint32_t af[MI][4];
#pragma unroll
            for (int i = 0; i < MI; i++) {
                uint32_t row = wm * WTM + i * 16 + (lane & 15);
                uint32_t kb  = ks * 32 + ((lane >> 4) << 4);
                ldsm_x4(af[i], baseA + sw128(row * 128 + kb));
            }
            uint32_t bf[NJ][2];
#pragma unroll
            for (int jp = 0; jp < NJ / 2; jp++) {
                uint32_t g = lane >> 3;
                uint32_t row = wn * WTN + jp * 16 + ((g >> 1) << 3) + (lane & 7);
                uint32_t kb  = ks * 32 + ((g & 1) << 4);
                uint32_t tmp[4];
                ldsm_x4(tmp, baseB + sw128(row * 128 + kb));
                bf[jp * 2][0] = tmp[0]; bf[jp * 2][1] = tmp[1];
                bf[jp * 2 + 1][0] = tmp[2]; bf[jp * 2 + 1][1] = tmp[3];
            }
#pragma unroll
            for (int i = 0; i < MI; i++)
#pragma unroll
                for (int j = 0; j < NJ; j++)
                    mma16816(acc[i][j], af[i], bf[j]);
        }
    }

#pragma unroll
    for (int i = 0; i < MI; i++) {
        const int r0 = rowBase + wm * WTM + i * 16 + (lane >> 2);
#pragma unroll
        for (int j = 0; j < NJ; j++) {
            const int col = colBase + wn * WTN + j * 8 + (lane & 3) * 2;
            const float b0 = bias[col], b1 = bias[col + 1];
            float v0 = acc[i][j][0] + b0, v1 = acc[i][j][1] + b1;
            float v2 = acc[i][j][2] + b0, v3 = acc[i][j][3] + b1;
            if (RELU) {
                v0 = fmaxf(v0, 0.f); v1 = fmaxf(v1, 0.f);
                v2 = fmaxf(v2, 0.f); v3 = fmaxf(v3, 0.f);
            }
            *(__nv_bfloat162*)&C[(size_t)r0 * ldc + col]       = __floats2bfloat162_rn(v0, v1);
            *(__nv_bfloat162*)&C[(size_t)(r0 + 8) * ldc + col] = __floats2bfloat162_rn(v2, v3);
        }
    }
}

// ---------------- VQ + dec1 + dec2 + MSE, fully fused -----------------------
// Phase 1: argmin over 4096 codes (mma scores, 3-stage codebook stream).
// Phase 2: gather q -> smem (+commit loss).
// Phase 3: h2 = relu(q @ d1t^T + db1) -> smem (8 swizzled 16KB k-blocks).
// Phase 4: x_hat = h2 @ d2t^T + db2, fused sum((x_hat - x)^2) -> g_mse_acc;
//          d2t streamed 3-stage through the freed codebook buffers.
__global__ void __launch_bounds__(256, 1) vq_mma(
    const __nv_bfloat16* __restrict__ Z0,
    const __nv_bfloat16* __restrict__ CBb0,
    const float* __restrict__ CBf0,
    const float* __restrict__ cn0,
    const __nv_bfloat16* __restrict__ D1t0,
    const float* __restrict__ db1_0,
    const __nv_bfloat16* __restrict__ D2t0,
    const float* __restrict__ db2_0,
    const __nv_bfloat16* __restrict__ Xb0)
{
    constexpr uint32_t Z_OFF  = 0;
    constexpr uint32_t CB_OFF = 16384;          // 3 x 16KB stream bufs
    constexpr uint32_t CN_OFF = 65536;          // 16KB
    constexpr uint32_t RV_OFF = 81920;
    constexpr uint32_t RI_OFF = 83968;
    constexpr uint32_t H2_OFF = 86016;          // 8 x 16KB = 128KB

    extern __shared__ char sm[];
    const uint32_t smb = smem_to_u32(sm);
    float* cn_s = (float*)(sm + CN_OFF);
    float* rv   = (float*)(sm + RV_OFF);
    int*   ri   = (int*)  (sm + RI_OFF);

    const int lvl = blockIdx.y;
    const __nv_bfloat16* Z   = Z0  + (size_t)lvl * NTOK * ND;
    const __nv_bfloat16* CBb = CBb0 + (size_t)lvl * NCB * ND;
    const float*         CBf = CBf0 + (size_t)lvl * NCB * ND;
    const float*         cn  = cn0 + (size_t)lvl * NCB;
    const __nv_bfloat16* D1  = D1t0 + (size_t)lvl * NH * ND;
    const float*         db1 = db1_0 + (size_t)lvl * NH;
    const __nv_bfloat16* D2  = D2t0 + (size_t)lvl * NF * NH;
    const float*         db2 = db2_0 + (size_t)lvl * NF;
    const __nv_bfloat16* Xb  = Xb0 + (size_t)lvl * NF;
    const int do_commit = (lvl == LVLS - 1);

    const int tid  = threadIdx.x;
    const int lane = tid & 31;
    const int wid  = tid >> 5;
    const int wm   = wid >> 2;      // 0..1
    const int wn   = wid & 3;       // 0..3
    const int r0   = blockIdx.x * 128;

    for (int i = tid; i < NCB / 4; i += 256)
        *(float4*)&cn_s[i * 4] = ((const float4*)cn)[i];

    auto copy_chunk = [&](int c) {
        const char* Cg = (const char*)(CBb + (size_t)c * 128 * ND);
        const uint32_t off = CB_OFF + (c % 3) * 16384;
        for (int idx = tid; idx < 128 * 8; idx += 256) {
            int r = idx >> 3, u = idx & 7;
            cp16(smb + off + sw128(r * 128 + u * 16), Cg + (size_t)r * 128 + u * 16);
        }
        CP_COMMIT();
    };

    {   // group 0: z + chunk0 ; group 1: chunk1
        const char* Zg = (const char*)(Z + (size_t)r0 * ND);
        for (int idx = tid; idx < 128 * 8; idx += 256) {
            int r = idx >> 3, u = idx & 7;
            cp16(smb + Z_OFF + sw128(r * 128 + u * 16), Zg + (size_t)r * 128 + u * 16);
        }
        const char* Cg = (const char*)CBb;
        for (int idx = tid; idx < 128 * 8; idx += 256) {
            int r = idx >> 3, u = idx & 7;
            cp16(smb + CB_OFF + sw128(r * 128 + u * 16), Cg + (size_t)r * 128 + u * 16);
        }
        CP_COMMIT();
        copy_chunk(1);
    }

    float minv[8];
    int   mini[8];
#pragma unroll
    for (int s = 0; s < 8; s++) { minv[s] = 3.4e38f; mini[s] = 0; }

    // ---- Phase 1: argmin over 32 codebook chunks ---------------------------
    for (int c = 0; c < 32; c++) {
        if (c + 1 < 32) CP_WAIT1(); else CP_WAIT0();
        __syncthreads();
        if (c + 2 < 32) copy_chunk(c + 2);

        const uint32_t baseB = smb + CB_OFF + (c % 3) * 16384;
        float acc[4][4][4];
#pragma unroll
        for (int i = 0; i < 4; i++)
#pragma unroll
            for (int j = 0; j < 4; j++)
#pragma unroll
                for (int k = 0; k < 4; k++) acc[i][j][k] = 0.f;

#pragma unroll
        for (int ks = 0; ks < 4; ks++) {
            uint32_t af[4][4];
#pragma unroll
            for (int i = 0; i < 4; i++) {
                uint32_t row = wm * 64 + i * 16 + (lane & 15);
                uint32_t kb  = ks * 32 + ((lane >> 4) << 4);
                ldsm_x4(af[i], smb + Z_OFF + sw128(row * 128 + kb));
            }
            uint32_t bfr[4][2];
#pragma unroll
            for (int jp = 0; jp < 2; jp++) {
                uint32_t g = lane >> 3;
                uint32_t row = wn * 32 + jp * 16 + ((g >> 1) << 3) + (lane & 7);
                uint32_t kb  = ks * 32 + ((g & 1) << 4);
                uint32_t tmp[4];
                ldsm_x4(tmp, baseB + sw128(row * 128 + kb));
                bfr[jp * 2][0] = tmp[0]; bfr[jp * 2][1] = tmp[1];
                bfr[jp * 2 + 1][0] = tmp[2]; bfr[jp * 2 + 1][1] = tmp[3];
            }
#pragma unroll
            for (int i = 0; i < 4; i++)
#pragma unroll
                for (int j = 0; j < 4; j++)
                    mma16816(acc[i][j], af[i], bfr[j]);
        }

#pragma unroll
        for (int j = 0; j < 4; j++) {
            const int code = c * 128 + wn * 32 + j * 8 + (lane & 3) * 2;
            float2 cn2 = *(const float2*)&cn_s[code & (NCB - 1)];
#pragma unroll
            for (int i = 0; i < 4; i++) {
                float d0 = fmaf(-2.f, acc[i][j][0], cn2.x);
                float d1 = fmaf(-2.f, acc[i][j][1], cn2.y);
                float d2 = fmaf(-2.f, acc[i][j][2], cn2.x);
                float d3 = fmaf(-2.f, acc[i][j][3], cn2.y);
                int s0 = i * 2, s1 = i * 2 + 1;
                if (d0 < minv[s0]) { minv[s0] = d0; mini[s0] = code; }
                if (d1 < minv[s0]) { minv[s0] = d1; mini[s0] = code + 1; }
                if (d2 < minv[s1]) { minv[s1] = d2; mini[s1] = code; }
                if (d3 < minv[s1]) { minv[s1] = d3; mini[s1] = code + 1; }
            }
        }
    }

    // cross-lane argmin reduce
#pragma unroll
    for (int s = 0; s < 8; s++) {
#pragma unroll
        for (int o = 1; o <= 2; o <<= 1) {
            float v  = __shfl_xor_sync(0xffffffffu, minv[s], o);
            int   ix = __shfl_xor_sync(0xffffffffu, mini[s], o);
            if (v < minv[s] || (v == minv[s] && ix < mini[s])) { minv[s] = v; mini[s] = ix; }
        }
    }
    if ((lane & 3) == 0) {
#pragma unroll
        for (int s = 0; s < 8; s++) {
            int row = wm * 64 + (s >> 1) * 16 + (s & 1) * 8 + (lane >> 2);
            rv[row * 4 + wn] = minv[s];
            ri[row * 4 + wn] = mini[s];
        }
    }
    __syncthreads();   // chunk reads done; rv/ri visible; CB buffers free

    // ---- Phase 2/3 prologue: stream dw1 into buffers 1/2 -------------------
    auto copy_dw1 = [&](int nc) {
        const char* Dg = (const char*)D1 + (size_t)nc * 128 * 128;
        const uint32_t off = CB_OFF + 16384 + (nc & 1) * 16384;      // buf1 / buf2
        for (int idx = tid; idx < 128 * 8; idx += 256) {
            int r = idx >> 3, u = idx & 7;
            cp16(smb + off + sw128(r * 128 + u * 16), Dg + r * 128 + u * 16);
        }
        CP_COMMIT();
    };
    copy_dw1(0);
    copy_dw1(1);

    // final per-row argmin + gather q -> smem buf0 (+ commit loss)
    if (tid < 128) {
        float bv = rv[tid * 4]; int bi = ri[tid * 4];
#pragma unroll
        for (int w = 1; w < 4; w++) {
            float v = rv[tid * 4 + w]; int ix = ri[tid * 4 + w];
            if (v < bv || (v == bv && ix < bi)) { bv = v; bi = ix; }
        }
        const float* crow = CBf + (size_t)bi * ND;
        float lsum = 0.f;
#pragma unroll
        for (int u = 0; u < 8; u++) {
            union { uint4 u4; __nv_bfloat16 b[8]; } Zr;
            Zr.u4 = *(const uint4*)(sm + Z_OFF + sw128(tid * 128 + u * 16));
            union { uint4 u4; __nv_bfloat162 h[4]; } Qo;
#pragma unroll
            for (int k = 0; k < 4; k++) {
                float a = crow[u * 8 + 2 * k];
                float b = crow[u * 8 + 2 * k + 1];
                Qo.h[k] = __floats2bfloat162_rn(a, b);
                if (do_commit) {
                    float d0 = a - __bfloat162float(Zr.b[2 * k]);
                    float d1 = b - __bfloat162float(Zr.b[2 * k + 1]);
                    lsum += d0 * d0 + d1 * d1;
                }
            }
            *(uint4*)(sm + CB_OFF + sw128(tid * 128 + u * 16)) = Qo.u4;   // q tile
        }
        if (do_commit) {
#pragma unroll
            for (int o = 16; o > 0; o >>= 1) lsum += __shfl_xor_sync(0xffffffffu, lsum, o);
            if (lane == 0) atomicAdd(&g_commit_acc, (double)lsum);
        }
    }
    __syncthreads();   // q tile visible

    // ---- Phase 3: h2[128x512] = relu(q @ d1t^T + db1) -> smem blocks -------
#pragma unroll
    for (int nc = 0; nc < 4; nc++) {
        if (nc < 3) CP_WAIT1(); else CP_WAIT0();
        __syncthreads();   // dw1 chunk nc visible

        const uint32_t baseB = smb + CB_OFF + 16384 + (nc & 1) * 16384;
        float acc[4][4][4];
#pragma unroll
        for (int i = 0; i < 4; i++)
#pragma unroll
            for (int j = 0; j < 4; j++)
#pragma unroll
                for (int k = 0; k < 4; k++) acc[i][j][k] = 0.f;

#pragma unroll
        for (int ks = 0; ks < 4; ks++) {
            uint32_t af[4][4];
#pragma unroll
            for (int i = 0; i < 4; i++) {
                uint32_t row = wm * 64 + i * 16 + (lane & 15);
                uint32_t kb  = ks * 32 + ((lane >> 4) << 4);
                ldsm_x4(af[i], smb + CB_OFF + sw128(row * 128 + kb));   // q tile
            }
            uint32_t bfr[4][2];
#pragma unroll
            for (int jp = 0; jp < 2; jp++) {
                uint32_t g = lane >> 3;
                uint32_t row = wn * 32 + jp * 16 + ((g >> 1) << 3) + (lane & 7);
                uint32_t kb  = ks * 32 + ((g & 1) << 4);
                uint32_t tmp[4];
                ldsm_x4(tmp, baseB + sw128(row * 128 + kb));
                bfr[jp * 2][0] = tmp[0]; bfr[jp * 2][1] = tmp[1];
                bfr[jp * 2 + 1][0] = tmp[2]; bfr[jp * 2 + 1][1] = tmp[3];
            }
#pragma unroll
            for (int i = 0; i < 4; i++)
#pragma unroll
                for (int j = 0; j < 4; j++)
                    mma16816(acc[i][j], af[i], bfr[j]);
        }
        __syncthreads();                 // reads of buf(nc&1) done
        if (nc + 2 < 4) copy_dw1(nc + 2);

        // write h2 chunk into smem k-blocks (64-col blocks, swizzled 128B rows)
#pragma unroll
        for (int i = 0; i < 4; i++) {
            const int row = wm * 64 + i * 16 + (lane >> 2);      // local 0..127
#pragma unroll
            for (int j = 0; j < 4; j++) {
                const int col = nc * 128 + wn * 32 + j * 8 + (lane & 3) * 2;
                const int kt  = col >> 6, loc = col & 63;
                const float b0 = db1[col], b1 = db1[col + 1];
                float v0 = fmaxf(acc[i][j][0] + b0, 0.f), v1 = fmaxf(acc[i][j][1] + b1, 0.f);
                float v2 = fmaxf(acc[i][j][2] + b0, 0.f), v3 = fmaxf(acc[i][j][3] + b1, 0.f);
                *(__nv_bfloat162*)(sm + H2_OFF + kt * 16384 + sw128(row * 128 + loc * 2))
                    = __floats2bfloat162_rn(v0, v1);
                *(__nv_bfloat162*)(sm + H2_OFF + kt * 16384 + sw128((row + 8) * 128 + loc * 2))
                    = __floats2bfloat162_rn(v2, v3);
            }
        }
    }
    __syncthreads();   // h2 blocks visible; all stream buffers free

    // ---- Phase 4: x_hat = h2 @ d2t^T + db2, fused MSE ----------------------
    auto copy_d2 = [&](int t) {            // t = nc2*8 + kt
        const int nc2 = t >> 3, kt = t & 7;
        const char* Dg = (const char*)D2 + ((size_t)(nc2 * 128) * NH + kt * 64) * 2;
        const uint32_t off = CB_OFF + (t % 3) * 16384;
        for (int idx = tid; idx < 128 * 8; idx += 256) {
            int r = idx >> 3, u = idx & 7;
            cp16(smb + off + sw128(r * 128 + u * 16), Dg + (size_t)r * NH * 2 + u * 16);
        }
        CP_COMMIT();
    };
    copy_d2(0);
    copy_d2(1);

    float msum = 0.f;
#pragma unroll
    for (int nc2 = 0; nc2 < 4; nc2++) {
        float acc[4][4][4];
#pragma unroll
        for (int i = 0; i < 4; i++)
#pragma unroll
            for (int j = 0; j < 4; j++)
#pragma unroll
                for (int k = 0; k < 4; k++) acc[i][j][k] = 0.f;

#pragma unroll
        for (int kt = 0; kt < 8; kt++) {
            const int t = nc2 * 8 + kt;
            if (t + 1 < 32) CP_WAIT1(); else CP_WAIT0();
            __syncthreads();
            if (t + 2 < 32) copy_d2(t + 2);
            const uint32_t baseA = smb + H2_OFF + kt * 16384;
            const uint32_t baseB = smb + CB_OFF + (t % 3) * 16384;
#pragma unroll
            for (int ks = 0; ks < 4; ks++) {
                uint32_t af[4][4];
#pragma unroll
                for (int i = 0; i < 4; i++) {
                    uint32_t row = wm * 64 + i * 16 + (lane & 15);
                    uint32_t kb  = ks * 32 + ((lane >> 4) << 4);
                    ldsm_x4(af[i], baseA + sw128(row * 128 + kb));
                }
                uint32_t bfr[4][2];
#pragma unroll
                for (int jp = 0; jp < 2; jp++) {
                    uint32_t g = lane >> 3;
                    uint32_t row = wn * 32 + jp * 16 + ((g >> 1) << 3) + (lane & 7);
                    uint32_t kb  = ks * 32 + ((g & 1) << 4);
                    uint32_t tmp[4];
                    ldsm_x4(tmp, baseB + sw128(row * 128 + kb));
                    bfr[jp * 2][0] = tmp[0]; bfr[jp * 2][1] = tmp[1];
                    bfr[jp * 2 + 1][0] = tmp[2]; bfr[jp * 2 + 1][1] = tmp[3];
                }
#pragma unroll
                for (int i = 0; i < 4; i++)
#pragma unroll
                    for (int j = 0; j < 4; j++)
                        mma16816(acc[i][j], af[i], bfr[j]);
            }
        }

        // MSE epilogue for this 128-col chunk
#pragma unroll
        for (int i = 0; i < 4; i++) {
            const int row = r0 + wm * 64 + i * 16 + (lane >> 2);
#pragma unroll
            for (int j = 0; j < 4; j++) {
                const int col = nc2 * 128 + wn * 32 + j * 8 + (lane & 3) * 2;
                const float b0 = db2[col], b1 = db2[col + 1];
                float v0 = acc[i][j][0] + b0, v1 = acc[i][j][1] + b1;
                float v2 = acc[i][j][2] + b0, v3 = acc[i][j][3] + b1;
                __nv_bfloat162 x0 = *(const __nv_bfloat162*)&Xb[(size_t)row * 2048 + col];
                __nv_bfloat162 x1 = *(const __nv_bfloat162*)&Xb[(size_t)(row + 8) * 2048 + col];
                float d0 = v0 - __bfloat162float(x0.x), d1 = v1 - __bfloat162float(x0.y);
                float d2 = v2 - __bfloat162float(x1.x), d3 = v3 - __bfloat162float(x1.y);
                msum += d0 * d0 + d1 * d1 + d2 * d2 + d3 * d3;
            }
        }
    }
#pragma unroll
    for (int o = 16; o > 0; o >>= 1) msum += __shfl_xor_sync(0xffffffffu, msum, o);
    if (lane == 0) atomicAdd(&g_mse_acc, (double)msum);
}

__global__ void finalize_kernel(float* out) {
    out[0] = (float)(g_mse_acc / ((double)NTOK * NF * LVLS));
    out[1] = (float)(0.25 * g_commit_acc / ((double)NTOK * ND * LVLS));
}

// ---------------------------------------------------------------------------
extern "C" void kernel_launch(void* const* d_in, const int* in_sizes, int n_in,
                              void* d_out, int out_size)
{
    const float* x   = (const float*)d_in[0];
    const float* ew1 = (const float*)d_in[1];
    const float* eb1 = (const float*)d_in[2];
    const float* ew2 = (const float*)d_in[3];
    const float* eb2 = (const float*)d_in[4];
    const float* dw1 = (const float*)d_in[5];
    const float* db1 = (const float*)d_in[6];
    const float* dw2 = (const float*)d_in[7];
    const float* db2 = (const float*)d_in[8];
    const float* cb  = (const float*)d_in[9];
    float* out = (float*)d_out;

    __nv_bfloat16 *xb, *hb, *zb, *w1t, *w2t, *d1t, *d2t, *cbb;
    float* cnp;
    cudaGetSymbolAddress((void**)&xb,  g_xb);
    cudaGetSymbolAddress((void**)&hb,  g_hb);
    cudaGetSymbolAddress((void**)&zb,  g_zb);
    cudaGetSymbolAddress((void**)&w1t, g_w1t);
    cudaGetSymbolAddress((void**)&w2t, g_w2t);
    cudaGetSymbolAddress((void**)&d1t, g_d1t);
    cudaGetSymbolAddress((void**)&d2t, g_d2t);
    cudaGetSymbolAddress((void**)&cbb, g_cbb);
    cudaGetSymbolAddress((void**)&cnp, g_cnorm);

    const int SMEM_128 = 3 * (16384 + 16384);   // 96KB
    const int SMEM_64  = 3 * (16384 + 8192);    // 72KB
    const int SMEM_VQ  = 86016 + 131072;        // 212KB
    cudaFuncSetAttribute(gemm_mma<512, 128, 2, 4, true >, cudaFuncAttributeMaxDynamicSharedMemorySize, SMEM_128);
    cudaFuncSetAttribute(gemm_mma<512, 64,  4, 2, false>, cudaFuncAttributeMaxDynamicSharedMemorySize, SMEM_64);
    cudaFuncSetAttribute(vq_mma, cudaFuncAttributeMaxDynamicSharedMemorySize, SMEM_VQ);

    // prelude: conversions / transposes / norms (+ accumulator init in cb_prep)
    cb_prep_kernel<<<(LVLS * NCB) / 256, 256>>>(cb, cbb);
    {
        int n4 = NTOK * 2048 / 4;
        conv_bf16_kernel<<<n4 / 256, 256>>>((const float4*)x, (uint2*)xb, n4);
    }
    transpose_conv2_kernel<<<dim3(16, 16, 2 * LVLS), dim3(32, 8)>>>(ew1, w1t, dw2, d2t);
    transpose_thin_kernel<<<dim3(16, 16, 2 * LVLS), dim3(32, 8)>>>(ew2, w2t, dw1, d1t);

    // h = relu(x_l @ ew1 + b1)  — all levels in one launch
    gemm_mma<512, 128, 2, 4, true><<<dim3(NH / 128, NTOK / 128, LVLS), 256, SMEM_128>>>(
        xb, 2048, (size_t)NF,
        w1t, (size_t)NH * NF,
        eb1, NH,
        hb, NH, (size_t)NTOK * NH);

    // z = h @ ew2 + b2
    gemm_mma<512, 64, 4, 2, false><<<dim3(1, NTOK / 128, LVLS), 256, SMEM_64>>>(
        hb, NH, (size_t)NTOK * NH,
        w2t, (size_t)ND * NH,
        eb2, ND,
        zb, ND, (size_t)NTOK * ND);

    // VQ + dec1 + dec2 + MSE fused
    vq_mma<<<dim3(NTOK / 128, LVLS), 256, SMEM_VQ>>>(
        zb, cbb, cb, cnp, d1t, db1, d2t, db2, xb);

    finalize_kernel<<<1, 1>>>(out);
}

// round 14
// speedup vs baseline: 1.0527x; 1.0527x over previous
#include <cuda_runtime.h>
#include <cuda_bf16.h>
#include <cstdint>

#define NTOK 32768
#define LVLS 4
#define NF   512
#define NH   512
#define ND   64
#define NCB  4096

// ---------------- scratch (device globals; no allocation allowed) ----------
__device__ __align__(16) __nv_bfloat16 g_xb [NTOK * 2048];            // x bf16
__device__ __align__(16) __nv_bfloat16 g_hb [LVLS * NTOK * NH];       // 128MB
__device__ __align__(16) __nv_bfloat16 g_zb [LVLS * NTOK * ND];
__device__ __align__(16) __nv_bfloat16 g_h2b[LVLS * NTOK * NH];       // 128MB
__device__ __align__(16) __nv_bfloat16 g_w1t[LVLS * NH * NF];         // [N][K]
__device__ __align__(16) __nv_bfloat16 g_w2t[LVLS * ND * NH];
__device__ __align__(16) __nv_bfloat16 g_d1t[LVLS * NH * ND];
__device__ __align__(16) __nv_bfloat16 g_d2t[LVLS * NF * NH];
__device__ __align__(16) __nv_bfloat16 g_cbb[LVLS * NCB * ND];
__device__ float  g_cnorm[LVLS * NCB];
__device__ double g_mse_acc;
__device__ double g_commit_acc;

// ---------------- helpers ---------------------------------------------------
__device__ __forceinline__ uint32_t smem_to_u32(const void* p) {
    uint32_t a;
    asm("{ .reg .u64 t; cvta.to.shared.u64 t, %1; cvt.u32.u64 %0, t; }" : "=r"(a) : "l"(p));
    return a;
}
__device__ __forceinline__ uint32_t sw128(uint32_t o) { return o ^ ((o >> 3) & 0x70); }

__device__ __forceinline__ void cp16(uint32_t dst, const void* src) {
    asm volatile("cp.async.cg.shared.global [%0], [%1], 16;" :: "r"(dst), "l"(src) : "memory");
}
#define CP_COMMIT() asm volatile("cp.async.commit_group;" ::: "memory")
#define CP_WAIT0()  asm volatile("cp.async.wait_group 0;" ::: "memory")
#define CP_WAIT1()  asm volatile("cp.async.wait_group 1;" ::: "memory")

__device__ __forceinline__ void ldsm_x4(uint32_t* r, uint32_t addr) {
    asm volatile("ldmatrix.sync.aligned.m8n8.x4.shared.b16 {%0,%1,%2,%3}, [%4];"
        : "=r"(r[0]), "=r"(r[1]), "=r"(r[2]), "=r"(r[3]) : "r"(addr));
}
__device__ __forceinline__ void mma16816(float* c, const uint32_t* a, const uint32_t* b) {
    asm volatile("mma.sync.aligned.m16n8k16.row.col.f32.bf16.bf16.f32 "
        "{%0,%1,%2,%3}, {%4,%5,%6,%7}, {%8,%9}, {%0,%1,%2,%3};"
        : "+f"(c[0]), "+f"(c[1]), "+f"(c[2]), "+f"(c[3])
        : "r"(a[0]), "r"(a[1]), "r"(a[2]), "r"(a[3]), "r"(b[0]), "r"(b[1]));
}

// ---------------- small kernels ---------------------------------------------
__global__ void conv_bf16_kernel(const float4* __restrict__ in, uint2* __restrict__ out, int n4) {
    int i = blockIdx.x * blockDim.x + threadIdx.x;
    if (i < n4) {
        float4 v = in[i];
        __nv_bfloat162 a = __floats2bfloat162_rn(v.x, v.y);
        __nv_bfloat162 b = __floats2bfloat162_rn(v.z, v.w);
        uint2 o; o.x = *(uint32_t*)&a; o.y = *(uint32_t*)&b;
        out[i] = o;
    }
}

// codebook: fp32 -> bf16 copy + squared norms + accumulator init, one pass
__global__ void cb_prep_kernel(const float* __restrict__ CB, __nv_bfloat16* __restrict__ CBb) {
    int c = blockIdx.x * blockDim.x + threadIdx.x;   // over LVLS*NCB rows
    if (c == 0) { g_mse_acc = 0.0; g_commit_acc = 0.0; }
    if (c < LVLS * NCB) {
        const float4* p = (const float4*)(CB + (size_t)c * ND);
        __nv_bfloat162* o = (__nv_bfloat162*)(CBb + (size_t)c * ND);
        float s = 0.f;
#pragma unroll
        for (int k = 0; k < ND / 4; k++) {
            float4 v = p[k];
            s += v.x * v.x + v.y * v.y + v.z * v.z + v.w * v.w;
            o[k * 2]     = __floats2bfloat162_rn(v.x, v.y);
            o[k * 2 + 1] = __floats2bfloat162_rn(v.z, v.w);
        }
        g_cnorm[c] = s;
    }
}

// two 512x512 weight sets (ew1, dw2) in one launch: blockIdx.z in [0, 2*LVLS)
__global__ void transpose_conv2_kernel(const float* __restrict__ Wa, __nv_bfloat16* __restrict__ Oa,
                                       const float* __restrict__ Wb, __nv_bfloat16* __restrict__ Ob) {
    __shared__ float ts[32][33];
    int z = blockIdx.z;
    const float* W  = (z < LVLS) ? Wa + (size_t)z * 512 * 512 : Wb + (size_t)(z - LVLS) * 512 * 512;
    __nv_bfloat16* O = (z < LVLS) ? Oa + (size_t)z * 512 * 512 : Ob + (size_t)(z - LVLS) * 512 * 512;
    int n0 = blockIdx.x * 32, k0 = blockIdx.y * 32;
    int tx = threadIdx.x, ty = threadIdx.y;
#pragma unroll
    for (int i = 0; i < 32; i += 8) ts[ty + i][tx] = W[(size_t)(k0 + ty + i) * 512 + n0 + tx];
    __syncthreads();
#pragma unroll
    for (int i = 0; i < 32; i += 8) O[(size_t)(n0 + ty + i) * 512 + k0 + tx] = __float2bfloat16(ts[tx][ty + i]);
}

// two thin weight sets (ew2: K=512,N=64 ; dw1: K=64,N=512), one launch.
__global__ void transpose_thin_kernel(const float* __restrict__ Wa, __nv_bfloat16* __restrict__ Oa,
                                      const float* __restrict__ Wb, __nv_bfloat16* __restrict__ Ob) {
    __shared__ float ts[32][33];
    int z = blockIdx.z;
    int K, N; const float* W; __nv_bfloat16* O;
    if (z < LVLS) { K = 512; N = 64;  W = Wa + (size_t)z * 512 * 64;  O = Oa + (size_t)z * 512 * 64; }
    else          { K = 64;  N = 512; W = Wb + (size_t)(z - LVLS) * 64 * 512; O = Ob + (size_t)(z - LVLS) * 64 * 512; }
    int n0 = blockIdx.x * 32, k0 = blockIdx.y * 32;
    if (n0 >= N || k0 >= K) return;
    int tx = threadIdx.x, ty = threadIdx.y;
#pragma unroll
    for (int i = 0; i < 32; i += 8) ts[ty + i][tx] = W[(size_t)(k0 + ty + i) * N + n0 + tx];
    __syncthreads();
#pragma unroll
    for (int i = 0; i < 32; i += 8) O[(size_t)(n0 + ty + i) * K + k0 + tx] = __float2bfloat16(ts[tx][ty + i]);
}

// ---------------- mma.sync GEMM, level-batched (blockIdx.z), 3-stage --------
// C[128-row tile, BN] = A @ Bt^T (+bias, relu / fused-MSE vs bf16 Xref).
// A bf16 row-major (lda), Bt bf16 [N][K] K-major. BK=64, K compile-time.
template<int K, int BN, int WM, int WN, bool RELU, bool MSE, int MAXB>
__global__ void __launch_bounds__(256, MAXB) gemm_mma(
    const __nv_bfloat16* __restrict__ A0, int lda, size_t aLvl,
    const __nv_bfloat16* __restrict__ Bt0, size_t bLvl,
    const float* __restrict__ bias0, int biasLvl,
    __nv_bfloat16* __restrict__ C0, int ldc, size_t cLvl,
    const __nv_bfloat16* __restrict__ X0, int ldx, size_t xLvl)
{
    constexpr int WTM = 128 / WM;
    constexpr int WTN = BN / WN;
    constexpr int MI  = WTM / 16;
    constexpr int NJ  = WTN / 8;
    constexpr int ABYTES = 128 * 128;
    constexpr int BBYTES = BN * 128;
    constexpr int STAGE  = ABYTES + BBYTES;
    constexpr int T = K / 64;

    extern __shared__ char sm[];
    const uint32_t smb = smem_to_u32(sm);

    const int lvl = blockIdx.z;
    const __nv_bfloat16* A    = A0 + (size_t)lvl * aLvl;
    const __nv_bfloat16* Bt   = Bt0 + (size_t)lvl * bLvl;
    const float*         bias = bias0 + (size_t)lvl * biasLvl;
    __nv_bfloat16*       C    = C0 ? C0 + (size_t)lvl * cLvl : nullptr;
    const __nv_bfloat16* Xref = X0 ? X0 + (size_t)lvl * xLvl : nullptr;

    const int tid  = threadIdx.x;
    const int lane = tid & 31;
    const int wid  = tid >> 5;
    const int wm   = wid / WN;
    const int wn   = wid % WN;
    const int rowBase = blockIdx.y * 128;
    const int colBase = blockIdx.x * BN;

    const char* Abase = (const char*)(A + (size_t)rowBase * lda);
    const char* Bbase = (const char*)(Bt + (size_t)colBase * K);

    auto copy_stage = [&](int t) {
        const uint32_t sb = smb + (t % 3) * STAGE;
        const char* Ag = Abase + t * 128;
        for (int idx = tid; idx < 128 * 8; idx += 256) {
            int r = idx >> 3, u = idx & 7;
            cp16(sb + sw128(r * 128 + u * 16), Ag + (size_t)r * lda * 2 + u * 16);
        }
        const char* Bg = Bbase + t * 128;
        for (int idx = tid; idx < BN * 8; idx += 256) {
            int r = idx >> 3, u = idx & 7;
            cp16(sb + ABYTES + sw128(r * 128 + u * 16), Bg + (size_t)r * K * 2 + u * 16);
        }
        CP_COMMIT();
    };

    float acc[MI][NJ][4];
#pragma unroll
    for (int i = 0; i < MI; i++)
#pragma unroll
        for (int j = 0; j < NJ; j++)
#pragma unroll
            for (int k = 0; k < 4; k++) acc[i][j][k] = 0.f;

    copy_stage(0);
    if (T > 1) copy_stage(1);

#pragma unroll
    for (int t = 0; t < T; t++) {
        if (t + 1 < T) CP_WAIT1(); else CP_WAIT0();
        __syncthreads();                       // stage t visible; prev compute done
        if (t + 2 < T) copy_stage(t + 2);      // into free buffer, overlaps compute
        const uint32_t baseA = smb + (t % 3) * STAGE;
        const uint32_t baseB = baseA + ABYTES;
#pragma unroll
        for (int ks = 0; ks < 4; ks++) {
            uint32_t af[MI][4];
#pragma unroll
            for (int i = 0; i < MI; i++) {
                uint32_t row = wm * WTM + i * 16 + (lane & 15);
                uint32_t kb  = ks * 32 + ((lane >> 4) << 4);
                ldsm_x4(af[i], baseA + sw128(row * 128 + kb));
            }
            uint32_t bf[NJ][2];
#pragma unroll
            for (int jp = 0; jp < NJ / 2; jp++) {
                uint32_t g = lane >> 3;
                uint32_t row = wn * WTN + jp * 16 + ((g >> 1) << 3) + (lane & 7);
                uint32_t kb  = ks * 32 + ((g & 1) << 4);
                uint32_t tmp[4];
                ldsm_x4(tmp, baseB + sw128(row * 128 + kb));
                bf[jp * 2][0] = tmp[0]; bf[jp * 2][1] = tmp[1];
                bf[jp * 2 + 1][0] = tmp[2]; bf[jp * 2 + 1][1] = tmp[3];
            }
#pragma unroll
            for (int i = 0; i < MI; i++)
#pragma unroll
                for (int j = 0; j < NJ; j++)
                    mma16816(acc[i][j], af[i], bf[j]);
        }
    }

    // epilogue
    float lsum = 0.f;
#pragma unroll
    for (int i = 0; i < MI; i++) {
        const int r0 = rowBase + wm * WTM + i * 16 + (lane >> 2);
#pragma unroll
        for (int j = 0; j < NJ; j++) {
            const int col = colBase + wn * WTN + j * 8 + (lane & 3) * 2;
            const float b0 = bias[col], b1 = bias[col + 1];
            float v0 = acc[i][j][0] + b0, v1 = acc[i][j][1] + b1;
            float v2 = acc[i][j][2] + b0, v3 = acc[i][j][3] + b1;
            if (MSE) {
                __nv_bfloat162 x0 = *(const __nv_bfloat162*)&Xref[(size_t)r0 * ldx + col];
                __nv_bfloat162 x1 = *(const __nv_bfloat162*)&Xref[(size_t)(r0 + 8) * ldx + col];
                float d0 = v0 - __bfloat162float(x0.x), d1 = v1 - __bfloat162float(x0.y);
                float d2 = v2 - __bfloat162float(x1.x), d3 = v3 - __bfloat162float(x1.y);
                lsum += d0 * d0 + d1 * d1 + d2 * d2 + d3 * d3;
            } else {
                if (RELU) {
                    v0 = fmaxf(v0, 0.f); v1 = fmaxf(v1, 0.f);
                    v2 = fmaxf(v2, 0.f); v3 = fmaxf(v3, 0.f);
                }
                *(__nv_bfloat162*)&C[(size_t)r0 * ldc + col]       = __floats2bfloat162_rn(v0, v1);
                *(__nv_bfloat162*)&C[(size_t)(r0 + 8) * ldc + col] = __floats2bfloat162_rn(v2, v3);
            }
        }
    }
    if (MSE) {
#pragma unroll
        for (int o = 16; o > 0; o >>= 1) lsum += __shfl_xor_sync(0xffffffffu, lsum, o);
        if (lane == 0) atomicAdd(&g_mse_acc, (double)lsum);
    }
}

// ---------------- VQ + dec1 fused, level-batched (blockIdx.y) ---------------
// Phase 1: argmin over 4096 codes (mma scores, 3-stage codebook stream).
// Phase 2: gather q -> smem (+commit loss), dw1 streamed into freed buffers.
// Phase 3: h2 = relu(q @ d1t^T + db1) -> gmem.
__global__ void __launch_bounds__(256, 2) vq_mma(
    const __nv_bfloat16* __restrict__ Z0,
    const __nv_bfloat16* __restrict__ CBb0,
    const float* __restrict__ CBf0,
    const float* __restrict__ cn0,
    const __nv_bfloat16* __restrict__ D1t0,
    const float* __restrict__ db1_0,
    __nv_bfloat16* __restrict__ H2_0)
{
    constexpr uint32_t Z_OFF  = 0;
    constexpr uint32_t CB_OFF = 16384;          // 3 x 16KB (buf0 becomes q-tile)
    constexpr uint32_t CN_OFF = 65536;          // 16KB
    constexpr uint32_t RV_OFF = 81920;
    constexpr uint32_t RI_OFF = 83968;

    extern __shared__ char sm[];
    const uint32_t smb = smem_to_u32(sm);
    float* cn_s = (float*)(sm + CN_OFF);
    float* rv   = (float*)(sm + RV_OFF);
    int*   ri   = (int*)  (sm + RI_OFF);

    const int lvl = blockIdx.y;
    const __nv_bfloat16* Z   = Z0  + (size_t)lvl * NTOK * ND;
    const __nv_bfloat16* CBb = CBb0 + (size_t)lvl * NCB * ND;
    const float*         CBf = CBf0 + (size_t)lvl * NCB * ND;
    const float*         cn  = cn0 + (size_t)lvl * NCB;
    const __nv_bfloat16* D1  = D1t0 + (size_t)lvl * NH * ND;
    const float*         db1 = db1_0 + (size_t)lvl * NH;
    __nv_bfloat16*       H2  = H2_0 + (size_t)lvl * NTOK * NH;
    const int do_commit = (lvl == LVLS - 1);

    const int tid  = threadIdx.x;
    const int lane = tid & 31;
    const int wid  = tid >> 5;
    const int wm   = wid >> 2;      // 0..1
    const int wn   = wid & 3;       // 0..3
    const int r0   = blockIdx.x * 128;

    for (int i = tid; i < NCB / 4; i += 256)
        *(float4*)&cn_s[i * 4] = ((const float4*)cn)[i];

    auto copy_chunk = [&](int c) {
        const char* Cg = (const char*)(CBb + (size_t)c * 128 * ND);
        const uint32_t off = CB_OFF + (c % 3) * 16384;
        for (int idx = tid; idx < 128 * 8; idx += 256) {
            int r = idx >> 3, u = idx & 7;
            cp16(smb + off + sw128(r * 128 + u * 16), Cg + (size_t)r * 128 + u * 16);
        }
        CP_COMMIT();
    };

    {   // group 0: z + chunk0 ; group 1: chunk1
        const char* Zg = (const char*)(Z + (size_t)r0 * ND);
        for (int idx = tid; idx < 128 * 8; idx += 256) {
            int r = idx >> 3, u = idx & 7;
            cp16(smb + Z_OFF + sw128(r * 128 + u * 16), Zg + (size_t)r * 128 + u * 16);
        }
        const char* Cg = (const char*)CBb;
        for (int idx = tid; idx < 128 * 8; idx += 256) {
            int r = idx >> 3, u = idx & 7;
            cp16(smb + CB_OFF + sw128(r * 128 + u * 16), Cg + (size_t)r * 128 + u * 16);
        }
        CP_COMMIT();
        copy_chunk(1);
    }

    float minv[8];
    int   mini[8];
#pragma unroll
    for (int s = 0; s < 8; s++) { minv[s] = 3.4e38f; mini[s] = 0; }

    // ---- Phase 1: argmin over 32 codebook chunks ---------------------------
    for (int c = 0; c < 32; c++) {
        if (c + 1 < 32) CP_WAIT1(); else CP_WAIT0();
        __syncthreads();
        if (c + 2 < 32) copy_chunk(c + 2);

        const uint32_t baseB = smb + CB_OFF + (c % 3) * 16384;
        float acc[4][4][4];
#pragma unroll
        for (int i = 0; i < 4; i++)
#pragma unroll
            for (int j = 0; j < 4; j++)
#pragma unroll
                for (int k = 0; k < 4; k++) acc[i][j][k] = 0.f;

#pragma unroll
        for (int ks = 0; ks < 4; ks++) {
            uint32_t af[4][4];
#pragma unroll
            for (int i = 0; i < 4; i++) {
                uint32_t row = wm * 64 + i * 16 + (lane & 15);
                uint32_t kb  = ks * 32 + ((lane >> 4) << 4);
                ldsm_x4(af[i], smb + Z_OFF + sw128(row * 128 + kb));
            }
            uint32_t bfr[4][2];
#pragma unroll
            for (int jp = 0; jp < 2; jp++) {
                uint32_t g = lane >> 3;
                uint32_t row = wn * 32 + jp * 16 + ((g >> 1) << 3) + (lane & 7);
                uint32_t kb  = ks * 32 + ((g & 1) << 4);
                uint32_t tmp[4];
                ldsm_x4(tmp, baseB + sw128(row * 128 + kb));
                bfr[jp * 2][0] = tmp[0]; bfr[jp * 2][1] = tmp[1];
                bfr[jp * 2 + 1][0] = tmp[2]; bfr[jp * 2 + 1][1] = tmp[3];
            }
#pragma unroll
            for (int i = 0; i < 4; i++)
#pragma unroll
                for (int j = 0; j < 4; j++)
                    mma16816(acc[i][j], af[i], bfr[j]);
        }

#pragma unroll
        for (int j = 0; j < 4; j++) {
            const int code = c * 128 + wn * 32 + j * 8 + (lane & 3) * 2;
            float2 cn2 = *(const float2*)&cn_s[code & (NCB - 1)];
#pragma unroll
            for (int i = 0; i < 4; i++) {
                float d0 = fmaf(-2.f, acc[i][j][0], cn2.x);
                float d1 = fmaf(-2.f, acc[i][j][1], cn2.y);
                float d2 = fmaf(-2.f, acc[i][j][2], cn2.x);
                float d3 = fmaf(-2.f, acc[i][j][3], cn2.y);
                int s0 = i * 2, s1 = i * 2 + 1;
                if (d0 < minv[s0]) { minv[s0] = d0; mini[s0] = code; }
                if (d1 < minv[s0]) { minv[s0] = d1; mini[s0] = code + 1; }
                if (d2 < minv[s1]) { minv[s1] = d2; mini[s1] = code; }
                if (d3 < minv[s1]) { minv[s1] = d3; mini[s1] = code + 1; }
            }
        }
    }

    // cross-lane argmin reduce
#pragma unroll
    for (int s = 0; s < 8; s++) {
#pragma unroll
        for (int o = 1; o <= 2; o <<= 1) {
            float v  = __shfl_xor_sync(0xffffffffu, minv[s], o);
            int   ix = __shfl_xor_sync(0xffffffffu, mini[s], o);
            if (v < minv[s] || (v == minv[s] && ix < mini[s])) { minv[s] = v; mini[s] = ix; }
        }
    }
    if ((lane & 3) == 0) {
#pragma unroll
        for (int s = 0; s < 8; s++) {
            int row = wm * 64 + (s >> 1) * 16 + (s & 1) * 8 + (lane >> 2);
            rv[row * 4 + wn] = minv[s];
            ri[row * 4 + wn] = mini[s];
        }
    }
    __syncthreads();   // chunk reads done; rv/ri visible; CB buffers free

    // ---- Phase 2/3 prologue: stream dw1 into buffers 1/2 -------------------
    auto copy_dw1 = [&](int nc) {
        const char* Dg = (const char*)D1 + (size_t)nc * 128 * 128;
        const uint32_t off = CB_OFF + 16384 + (nc & 1) * 16384;      // buf1 / buf2
        for (int idx = tid; idx < 128 * 8; idx += 256) {
            int r = idx >> 3, u = idx & 7;
            cp16(smb + off + sw128(r * 128 + u * 16), Dg + r * 128 + u * 16);
        }
        CP_COMMIT();
    };
    copy_dw1(0);
    copy_dw1(1);

    // final per-row argmin + gather q -> smem buf0 (+ commit loss)
    if (tid < 128) {
        float bv = rv[tid * 4]; int bi = ri[tid * 4];
#pragma unroll
        for (int w = 1; w < 4; w++) {
            float v = rv[tid * 4 + w]; int ix = ri[tid * 4 + w];
            if (v < bv || (v == bv && ix < bi)) { bv = v; bi = ix; }
        }
        const float* crow = CBf + (size_t)bi * ND;
        float lsum = 0.f;
#pragma unroll
        for (int u = 0; u < 8; u++) {
            union { uint4 u4; __nv_bfloat16 b[8]; } Zr;
            Zr.u4 = *(const uint4*)(sm + Z_OFF + sw128(tid * 128 + u * 16));
            union { uint4 u4; __nv_bfloat162 h[4]; } Qo;
#pragma unroll
            for (int k = 0; k < 4; k++) {
                float a = crow[u * 8 + 2 * k];
                float b = crow[u * 8 + 2 * k + 1];
                Qo.h[k] = __floats2bfloat162_rn(a, b);
                if (do_commit) {
                    float d0 = a - __bfloat162float(Zr.b[2 * k]);
                    float d1 = b - __bfloat162float(Zr.b[2 * k + 1]);
                    lsum += d0 * d0 + d1 * d1;
                }
            }
            *(uint4*)(sm + CB_OFF + sw128(tid * 128 + u * 16)) = Qo.u4;   // q tile
        }
        if (do_commit) {
#pragma unroll
            for (int o = 16; o > 0; o >>= 1) lsum += __shfl_xor_sync(0xffffffffu, lsum, o);
            if (lane == 0) atomicAdd(&g_commit_acc, (double)lsum);
        }
    }
    __syncthreads();   // q tile visible

    // ---- Phase 3: h2[128 x 512] = relu(q @ d1t^T + db1), 4 N-chunks --------
#pragma unroll
    for (int nc = 0; nc < 4; nc++) {
        if (nc < 3) CP_WAIT1(); else CP_WAIT0();
        __syncthreads();   // dw1 chunk nc visible

        const uint32_t baseB = smb + CB_OFF + 16384 + (nc & 1) * 16384;
        float acc[4][4][4];
#pragma unroll
        for (int i = 0; i < 4; i++)
#pragma unroll
            for (int j = 0; j < 4; j++)
#pragma unroll
                for (int k = 0; k < 4; k++) acc[i][j][k] = 0.f;

#pragma unroll
        for (int ks = 0; ks < 4; ks++) {
            uint32_t af[4][4];
#pragma unroll
            for (int i = 0; i < 4; i++) {
                uint32_t row = wm * 64 + i * 16 + (lane & 15);
                uint32_t kb  = ks * 32 + ((lane >> 4) << 4);
                ldsm_x4(af[i], smb + CB_OFF + sw128(row * 128 + kb));   // q tile
            }
            uint32_t bfr[4][2];
#pragma unroll
            for (int jp = 0; jp < 2; jp++) {
                uint32_t g = lane >> 3;
                uint32_t row = wn * 32 + jp * 16 + ((g >> 1) << 3) + (lane & 7);
                uint32_t kb  = ks * 32 + ((g & 1) << 4);
                uint32_t tmp[4];
                ldsm_x4(tmp, baseB + sw128(row * 128 + kb));
                bfr[jp * 2][0] = tmp[0]; bfr[jp * 2][1] = tmp[1];
                bfr[jp * 2 + 1][0] = tmp[2]; bfr[jp * 2 + 1][1] = tmp[3];
            }
#pragma unroll
            for (int i = 0; i < 4; i++)
#pragma unroll
                for (int j = 0; j < 4; j++)
                    mma16816(acc[i][j], af[i], bfr[j]);
        }
        __syncthreads();                 // all reads of buf(nc&1) done
        if (nc + 2 < 4) copy_dw1(nc + 2);

        // epilogue: write h2 chunk
#pragma unroll
        for (int i = 0; i < 4; i++) {
            const int row = r0 + wm * 64 + i * 16 + (lane >> 2);
#pragma unroll
            for (int j = 0; j < 4; j++) {
                const int col = nc * 128 + wn * 32 + j * 8 + (lane & 3) * 2;
                const float b0 = db1[col], b1 = db1[col + 1];
                float v0 = fmaxf(acc[i][j][0] + b0, 0.f), v1 = fmaxf(acc[i][j][1] + b1, 0.f);
                float v2 = fmaxf(acc[i][j][2] + b0, 0.f), v3 = fmaxf(acc[i][j][3] + b1, 0.f);
                *(__nv_bfloat162*)&H2[(size_t)row * NH + col]       = __floats2bfloat162_rn(v0, v1);
                *(__nv_bfloat162*)&H2[(size_t)(row + 8) * NH + col] = __floats2bfloat162_rn(v2, v3);
            }
        }
    }
}

__global__ void finalize_kernel(float* out) {
    out[0] = (float)(g_mse_acc / ((double)NTOK * NF * LVLS));
    out[1] = (float)(0.25 * g_commit_acc / ((double)NTOK * ND * LVLS));
}

// ---------------------------------------------------------------------------
extern "C" void kernel_launch(void* const* d_in, const int* in_sizes, int n_in,
                              void* d_out, int out_size)
{
    const float* x   = (const float*)d_in[0];
    const float* ew1 = (const float*)d_in[1];
    const float* eb1 = (const float*)d_in[2];
    const float* ew2 = (const float*)d_in[3];
    const float* eb2 = (const float*)d_in[4];
    const float* dw1 = (const float*)d_in[5];
    const float* db1 = (const float*)d_in[6];
    const float* dw2 = (const float*)d_in[7];
    const float* db2 = (const float*)d_in[8];
    const float* cb  = (const float*)d_in[9];
    float* out = (float*)d_out;

    __nv_bfloat16 *xb, *hb, *zb, *h2b, *w1t, *w2t, *d1t, *d2t, *cbb;
    float* cnp;
    cudaGetSymbolAddress((void**)&xb,  g_xb);
    cudaGetSymbolAddress((void**)&hb,  g_hb);
    cudaGetSymbolAddress((void**)&zb,  g_zb);
    cudaGetSymbolAddress((void**)&h2b, g_h2b);
    cudaGetSymbolAddress((void**)&w1t, g_w1t);
    cudaGetSymbolAddress((void**)&w2t, g_w2t);
    cudaGetSymbolAddress((void**)&d1t, g_d1t);
    cudaGetSymbolAddress((void**)&d2t, g_d2t);
    cudaGetSymbolAddress((void**)&cbb, g_cbb);
    cudaGetSymbolAddress((void**)&cnp, g_cnorm);

    const int SMEM_128 = 3 * (16384 + 16384);   // 96KB
    const int SMEM_64  = 3 * (16384 + 8192);    // 72KB
    const int SMEM_VQ  = 86016;                 // 84KB
    cudaFuncSetAttribute(gemm_mma<512, 128, 2, 4, true,  false, 2>, cudaFuncAttributeMaxDynamicSharedMemorySize, SMEM_128);
    cudaFuncSetAttribute(gemm_mma<512, 64,  4, 2, false, false, 3>, cudaFuncAttributeMaxDynamicSharedMemorySize, SMEM_64);
    cudaFuncSetAttribute(gemm_mma<512, 128, 2, 4, false, true,  2>, cudaFuncAttributeMaxDynamicSharedMemorySize, SMEM_128);
    cudaFuncSetAttribute(vq_mma, cudaFuncAttributeMaxDynamicSharedMemorySize, SMEM_VQ);

    // prelude: conversions / transposes / norms (+ accumulator init in cb_prep)
    cb_prep_kernel<<<(LVLS * NCB) / 256, 256>>>(cb, cbb);
    {
        int n4 = NTOK * 2048 / 4;
        conv_bf16_kernel<<<n4 / 256, 256>>>((const float4*)x, (uint2*)xb, n4);
    }
    transpose_conv2_kernel<<<dim3(16, 16, 2 * LVLS), dim3(32, 8)>>>(ew1, w1t, dw2, d2t);
    transpose_thin_kernel<<<dim3(16, 16, 2 * LVLS), dim3(32, 8)>>>(ew2, w2t, dw1, d1t);

    // h = relu(x_l @ ew1 + b1)  — all levels in one launch
    gemm_mma<512, 128, 2, 4, true, false, 2><<<dim3(NH / 128, NTOK / 128, LVLS), 256, SMEM_128>>>(
        xb, 2048, (size_t)NF,
        w1t, (size_t)NH * NF,
        eb1, NH,
        hb, NH, (size_t)NTOK * NH,
        nullptr, 0, 0);

    // z = h @ ew2 + b2   (3 CTA/SM)
    gemm_mma<512, 64, 4, 2, false, false, 3><<<dim3(1, NTOK / 128, LVLS), 256, SMEM_64>>>(
        hb, NH, (size_t)NTOK * NH,
        w2t, (size_t)ND * NH,
        eb2, ND,
        zb, ND, (size_t)NTOK * ND,
        nullptr, 0, 0);

    // VQ + dec1 fused: argmin, commit, h2 = relu(q @ dw1 + b1)
    vq_mma<<<dim3(NTOK / 128, LVLS), 256, SMEM_VQ>>>(zb, cbb, cb, cnp, d1t, db1, h2b);

    // mse += sum((h2 @ dw2 + b2 - x_l)^2)   (bf16 Xref)
    gemm_mma<512, 128, 2, 4, false, true, 2><<<dim3(NF / 128, NTOK / 128, LVLS), 256, SMEM_128>>>(
        h2b, NH, (size_t)NTOK * NH,
        d2t, (size_t)NF * NH,
        db2, NF,
        nullptr, 0, 0,
        xb, 2048, (size_t)NF);

    finalize_kernel<<<1, 1>>>(out);
}